// round 12
// baseline (speedup 1.0000x reference)
#include <cuda_runtime.h>
#include <cuda_bf16.h>
#include <cstdint>

// SSIM loss map: out = clip((1 - SSIM_3x3(x,y)) * 0.5, 0, 1)
// NCHW fp32, 16x3x512x512 = 48 planes of 512x512.
// Register-sliding, no shared memory, no shuffles: each thread loads its
// aligned mid float2 plus the two neighbor taps as SCALAR loads (L1-served
// overlap with adjacent threads). Packed f32x2 math, one-iteration software
// pipeline, (p+c, c) rolling vertical window, pointer + constant addressing.

#define IMG   512
#define ROWS  16          // output rows per thread
#define TPX   128         // threads per block; block covers TPX*2 = 256 cols

typedef unsigned long long u64;

// ---- packed f32x2 helpers (sm_100+) ----
__device__ __forceinline__ u64 pk(float x, float y) {
    u64 r; asm("mov.b64 %0, {%1, %2};" : "=l"(r) : "f"(x), "f"(y)); return r;
}
__device__ __forceinline__ float2 unpk(u64 v) {
    float2 r; asm("mov.b64 {%0, %1}, %2;" : "=f"(r.x), "=f"(r.y) : "l"(v)); return r;
}
__device__ __forceinline__ u64 add2(u64 a, u64 b) {
    u64 r; asm("add.rn.f32x2 %0, %1, %2;" : "=l"(r) : "l"(a), "l"(b)); return r;
}
__device__ __forceinline__ u64 sub2(u64 a, u64 b) {
    u64 r; asm("sub.rn.f32x2 %0, %1, %2;" : "=l"(r) : "l"(a), "l"(b)); return r;
}
__device__ __forceinline__ u64 mul2(u64 a, u64 b) {
    u64 r; asm("mul.rn.f32x2 %0, %1, %2;" : "=l"(r) : "l"(a), "l"(b)); return r;
}
__device__ __forceinline__ u64 fma2(u64 a, u64 b, u64 c) {
    u64 r; asm("fma.rn.f32x2 %0, %1, %2, %3;" : "=l"(r) : "l"(a), "l"(b), "l"(c)); return r;
}

// Raw row: mid pair + exactly the two neighbor taps, for both images. 8 regs.
struct Raw { float2 aM, bM; float aL, aR, bL, bR; };

// Horizontal 3-tap sums for the thread's 2 output columns, packed f32x2.
struct Stat { u64 x, y, xx, yy, xy; };

// Prefetch: LDGs only; doff is compile-time-constant at every call site.
__device__ __forceinline__ Raw load_raw(const float* __restrict__ px,
                                        const float* __restrict__ py,
                                        int doff, bool valid,
                                        bool okL, bool okR)
{
    Raw r;
    r.aM = make_float2(0.f, 0.f);
    r.bM = make_float2(0.f, 0.f);
    r.aL = r.aR = r.bL = r.bR = 0.f;
    if (valid) {
        r.aM = *(const float2*)(px + doff);
        r.bM = *(const float2*)(py + doff);
        if (okL) { r.aL = px[doff - 1]; r.bL = py[doff - 1]; }
        if (okR) { r.aR = px[doff + 2]; r.bR = py[doff + 2]; }
    }
    return r;
}

// Consume: pure register math on data loaded >= 1 iteration ago.
__device__ __forceinline__ Stat make_stats(const Raw& w)
{
    Stat s;
    float sa = w.aM.x + w.aM.y;
    s.x = pk(w.aL + sa, sa + w.aR);
    float sb = w.bM.x + w.bM.y;
    s.y = pk(w.bL + sb, sb + w.bR);
    float pa = fmaf(w.aM.x, w.aM.x, w.aM.y * w.aM.y);
    s.xx = pk(fmaf(w.aL, w.aL, pa), fmaf(w.aR, w.aR, pa));
    float pb = fmaf(w.bM.x, w.bM.x, w.bM.y * w.bM.y);
    s.yy = pk(fmaf(w.bL, w.bL, pb), fmaf(w.bR, w.bR, pb));
    float pm = fmaf(w.aM.x, w.bM.x, w.aM.y * w.bM.y);
    s.xy = pk(fmaf(w.aL, w.bL, pm), fmaf(w.aR, w.bR, pm));
    return s;
}

__global__ __launch_bounds__(TPX)
void ssim_kernel(const float* __restrict__ gx,
                 const float* __restrict__ gy,
                 float* __restrict__ gout)
{
    const int tx = threadIdx.x;
    const int c2 = blockIdx.x * TPX + tx;       // float2 column index, 0..255
    const bool okL = (c2 > 0);
    const bool okR = (c2 < IMG / 2 - 1);
    const int h0 = blockIdx.y * ROWS;

    // per-thread base pointers at (row h0, col 2*c2); all further addressing
    // is compile-time-constant offsets from these
    const size_t base = (size_t)blockIdx.z * (IMG * IMG);
    const int toff = h0 * IMG + 2 * c2;
    const float* px = gx + base + toff;
    const float* py = gy + base + toff;
    float2* pout = (float2*)(gout + base) + (h0 * (IMG / 2) + c2);

    const float THIRD = 1.f / 3.f;
    float2 rcx = make_float2(okL ? THIRD : 0.5f,
                             okR ? THIRD : 0.5f);

    const u64 TWO2 = pk(2.f, 2.f);
    const u64 C12  = pk(1e-4f, 1e-4f);
    const u64 C22  = pk(9e-4f, 9e-4f);
    const u64 inv3 = pk(rcx.x * THIRD, rcx.y * THIRD);   // interior rows

    // Pipeline fill. Rolling state: pc = stats(h-1)+stats(h), c = stats(h).
    Stat p0 = make_stats(load_raw(px, py, -IMG, h0 > 0, okL, okR));
    Stat c  = make_stats(load_raw(px, py, 0, true, okL, okR));
    Stat pc;
    pc.x  = add2(p0.x,  c.x);
    pc.y  = add2(p0.y,  c.y);
    pc.xx = add2(p0.xx, c.xx);
    pc.yy = add2(p0.yy, c.yy);
    pc.xy = add2(p0.xy, c.xy);
    Raw rn = load_raw(px, py, IMG, true, okL, okR);

    #pragma unroll
    for (int r = 0; r < ROWS; r++) {
        // prefetch row h0+r+2: in-bounds by construction except the last two
        // iterations of the last y-block (compile-time except the h0 compare)
        const bool valid = (r < ROWS - 2) || (h0 < IMG - ROWS);
        Raw rf = load_raw(px, py, (r + 2) * IMG, valid, okL, okR);

        // consume the row prefetched last iteration (registers only)
        Stat n = make_stats(rn);

        // normalization: cy != 3 only possible at iterations 0 and ROWS-1
        u64 inv = inv3;
        if ((r == 0 && h0 == 0) || (r == ROWS - 1 && h0 == IMG - ROWS))
            inv = pk(rcx.x * 0.5f, rcx.y * 0.5f);

        // vertical 3-tap totals and window shift
        u64 Sx  = add2(pc.x,  n.x);
        u64 Sy  = add2(pc.y,  n.y);
        u64 Sxx = add2(pc.xx, n.xx);
        u64 Syy = add2(pc.yy, n.yy);
        u64 Sxy = add2(pc.xy, n.xy);

        pc.x  = add2(c.x,  n.x);
        pc.y  = add2(c.y,  n.y);
        pc.xx = add2(c.xx, n.xx);
        pc.yy = add2(c.yy, n.yy);
        pc.xy = add2(c.xy, n.xy);
        c = n;

        // packed SSIM epilogue
        u64 mux = mul2(Sx, inv);
        u64 muy = mul2(Sy, inv);
        u64 mmx  = mul2(mux, mux);
        u64 mmy  = mul2(muy, muy);
        u64 mmxy = mul2(mux, muy);
        u64 sigx  = sub2(mul2(Sxx, inv), mmx);
        u64 sigy  = sub2(mul2(Syy, inv), mmy);
        u64 sigxy = sub2(mul2(Sxy, inv), mmxy);

        u64 t1  = fma2(mmxy, TWO2, C12);
        u64 t2  = fma2(sigxy, TWO2, C22);
        u64 num = mul2(t1, t2);
        u64 d1  = add2(add2(mmx, mmy), C12);
        u64 d2  = add2(add2(sigx, sigy), C22);
        u64 den = mul2(d1, d2);       // den >= C1*C2 >> 1e-12; eps is sub-ulp

        float2 fn = unpk(num);
        float2 fd = unpk(den);
        float2 o;
        o.x = __saturatef(fmaf(__fdividef(fn.x, fd.x), -0.5f, 0.5f));
        o.y = __saturatef(fmaf(__fdividef(fn.y, fd.y), -0.5f, 0.5f));

        pout[r * (IMG / 2)] = o;

        rn = rf;
    }
}

extern "C" void kernel_launch(void* const* d_in, const int* in_sizes, int n_in,
                              void* d_out, int out_size)
{
    const float* x = (const float*)d_in[0];
    const float* y = (const float*)d_in[1];
    float* out = (float*)d_out;

    dim3 block(TPX, 1, 1);                            // 128 threads
    dim3 grid(IMG / (2 * TPX), IMG / ROWS, 16 * 3);   // 2 x 32 x 48 = 3072
    ssim_kernel<<<grid, block>>>(x, y, out);
}

// round 13
// speedup vs baseline: 1.0147x; 1.0147x over previous
#include <cuda_runtime.h>
#include <cuda_bf16.h>
#include <cstdint>

// SSIM loss map: out = clip((1 - SSIM_3x3(x,y)) * 0.5, 0, 1)
// NCHW fp32, 16x3x512x512 = 48 planes of 512x512.
// Register-sliding, no shared memory, no shuffles: each thread loads its
// aligned mid float2 plus the two neighbor taps as SCALAR loads (L1-served
// overlap with adjacent threads). Packed f32x2 math, one-iteration software
// pipeline, (p+c, c) rolling vertical window, pointer + constant addressing.
// This round: __launch_bounds__(128, 8) to force 64 regs -> 8 blocks/SM.

#define IMG   512
#define ROWS  16          // output rows per thread
#define TPX   128         // threads per block; block covers TPX*2 = 256 cols

typedef unsigned long long u64;

// ---- packed f32x2 helpers (sm_100+) ----
__device__ __forceinline__ u64 pk(float x, float y) {
    u64 r; asm("mov.b64 %0, {%1, %2};" : "=l"(r) : "f"(x), "f"(y)); return r;
}
__device__ __forceinline__ float2 unpk(u64 v) {
    float2 r; asm("mov.b64 {%0, %1}, %2;" : "=f"(r.x), "=f"(r.y) : "l"(v)); return r;
}
__device__ __forceinline__ u64 add2(u64 a, u64 b) {
    u64 r; asm("add.rn.f32x2 %0, %1, %2;" : "=l"(r) : "l"(a), "l"(b)); return r;
}
__device__ __forceinline__ u64 sub2(u64 a, u64 b) {
    u64 r; asm("sub.rn.f32x2 %0, %1, %2;" : "=l"(r) : "l"(a), "l"(b)); return r;
}
__device__ __forceinline__ u64 mul2(u64 a, u64 b) {
    u64 r; asm("mul.rn.f32x2 %0, %1, %2;" : "=l"(r) : "l"(a), "l"(b)); return r;
}
__device__ __forceinline__ u64 fma2(u64 a, u64 b, u64 c) {
    u64 r; asm("fma.rn.f32x2 %0, %1, %2, %3;" : "=l"(r) : "l"(a), "l"(b), "l"(c)); return r;
}

// Raw row: mid pair + exactly the two neighbor taps, for both images. 8 regs.
struct Raw { float2 aM, bM; float aL, aR, bL, bR; };

// Horizontal 3-tap sums for the thread's 2 output columns, packed f32x2.
struct Stat { u64 x, y, xx, yy, xy; };

// Prefetch: LDGs only; doff is compile-time-constant at every call site.
__device__ __forceinline__ Raw load_raw(const float* __restrict__ px,
                                        const float* __restrict__ py,
                                        int doff, bool valid,
                                        bool okL, bool okR)
{
    Raw r;
    r.aM = make_float2(0.f, 0.f);
    r.bM = make_float2(0.f, 0.f);
    r.aL = r.aR = r.bL = r.bR = 0.f;
    if (valid) {
        r.aM = *(const float2*)(px + doff);
        r.bM = *(const float2*)(py + doff);
        if (okL) { r.aL = px[doff - 1]; r.bL = py[doff - 1]; }
        if (okR) { r.aR = px[doff + 2]; r.bR = py[doff + 2]; }
    }
    return r;
}

// Consume: pure register math on data loaded >= 1 iteration ago.
__device__ __forceinline__ Stat make_stats(const Raw& w)
{
    Stat s;
    float sa = w.aM.x + w.aM.y;
    s.x = pk(w.aL + sa, sa + w.aR);
    float sb = w.bM.x + w.bM.y;
    s.y = pk(w.bL + sb, sb + w.bR);
    float pa = fmaf(w.aM.x, w.aM.x, w.aM.y * w.aM.y);
    s.xx = pk(fmaf(w.aL, w.aL, pa), fmaf(w.aR, w.aR, pa));
    float pb = fmaf(w.bM.x, w.bM.x, w.bM.y * w.bM.y);
    s.yy = pk(fmaf(w.bL, w.bL, pb), fmaf(w.bR, w.bR, pb));
    float pm = fmaf(w.aM.x, w.bM.x, w.aM.y * w.bM.y);
    s.xy = pk(fmaf(w.aL, w.bL, pm), fmaf(w.aR, w.bR, pm));
    return s;
}

__global__ __launch_bounds__(TPX, 8)
void ssim_kernel(const float* __restrict__ gx,
                 const float* __restrict__ gy,
                 float* __restrict__ gout)
{
    const int tx = threadIdx.x;
    const int c2 = blockIdx.x * TPX + tx;       // float2 column index, 0..255
    const bool okL = (c2 > 0);
    const bool okR = (c2 < IMG / 2 - 1);
    const int h0 = blockIdx.y * ROWS;

    // per-thread base pointers at (row h0, col 2*c2); all further addressing
    // is compile-time-constant offsets from these
    const size_t base = (size_t)blockIdx.z * (IMG * IMG);
    const int toff = h0 * IMG + 2 * c2;
    const float* px = gx + base + toff;
    const float* py = gy + base + toff;
    float2* pout = (float2*)(gout + base) + (h0 * (IMG / 2) + c2);

    const float THIRD = 1.f / 3.f;
    float2 rcx = make_float2(okL ? THIRD : 0.5f,
                             okR ? THIRD : 0.5f);

    const u64 TWO2 = pk(2.f, 2.f);
    const u64 C12  = pk(1e-4f, 1e-4f);
    const u64 C22  = pk(9e-4f, 9e-4f);
    const u64 inv3 = pk(rcx.x * THIRD, rcx.y * THIRD);   // interior rows

    // Pipeline fill. Rolling state: pc = stats(h-1)+stats(h), c = stats(h).
    Stat p0 = make_stats(load_raw(px, py, -IMG, h0 > 0, okL, okR));
    Stat c  = make_stats(load_raw(px, py, 0, true, okL, okR));
    Stat pc;
    pc.x  = add2(p0.x,  c.x);
    pc.y  = add2(p0.y,  c.y);
    pc.xx = add2(p0.xx, c.xx);
    pc.yy = add2(p0.yy, c.yy);
    pc.xy = add2(p0.xy, c.xy);
    Raw rn = load_raw(px, py, IMG, true, okL, okR);

    #pragma unroll
    for (int r = 0; r < ROWS; r++) {
        // prefetch row h0+r+2: in-bounds by construction except the last two
        // iterations of the last y-block (compile-time except the h0 compare)
        const bool valid = (r < ROWS - 2) || (h0 < IMG - ROWS);
        Raw rf = load_raw(px, py, (r + 2) * IMG, valid, okL, okR);

        // consume the row prefetched last iteration (registers only)
        Stat n = make_stats(rn);

        // normalization: cy != 3 only possible at iterations 0 and ROWS-1
        u64 inv = inv3;
        if ((r == 0 && h0 == 0) || (r == ROWS - 1 && h0 == IMG - ROWS))
            inv = pk(rcx.x * 0.5f, rcx.y * 0.5f);

        // vertical 3-tap totals and window shift
        u64 Sx  = add2(pc.x,  n.x);
        u64 Sy  = add2(pc.y,  n.y);
        u64 Sxx = add2(pc.xx, n.xx);
        u64 Syy = add2(pc.yy, n.yy);
        u64 Sxy = add2(pc.xy, n.xy);

        pc.x  = add2(c.x,  n.x);
        pc.y  = add2(c.y,  n.y);
        pc.xx = add2(c.xx, n.xx);
        pc.yy = add2(c.yy, n.yy);
        pc.xy = add2(c.xy, n.xy);
        c = n;

        // packed SSIM epilogue
        u64 mux = mul2(Sx, inv);
        u64 muy = mul2(Sy, inv);
        u64 mmx  = mul2(mux, mux);
        u64 mmy  = mul2(muy, muy);
        u64 mmxy = mul2(mux, muy);
        u64 sigx  = sub2(mul2(Sxx, inv), mmx);
        u64 sigy  = sub2(mul2(Syy, inv), mmy);
        u64 sigxy = sub2(mul2(Sxy, inv), mmxy);

        u64 t1  = fma2(mmxy, TWO2, C12);
        u64 t2  = fma2(sigxy, TWO2, C22);
        u64 num = mul2(t1, t2);
        u64 d1  = add2(add2(mmx, mmy), C12);
        u64 d2  = add2(add2(sigx, sigy), C22);
        u64 den = mul2(d1, d2);       // den >= C1*C2 >> 1e-12; eps is sub-ulp

        float2 fn = unpk(num);
        float2 fd = unpk(den);
        float2 o;
        o.x = __saturatef(fmaf(__fdividef(fn.x, fd.x), -0.5f, 0.5f));
        o.y = __saturatef(fmaf(__fdividef(fn.y, fd.y), -0.5f, 0.5f));

        pout[r * (IMG / 2)] = o;

        rn = rf;
    }
}

extern "C" void kernel_launch(void* const* d_in, const int* in_sizes, int n_in,
                              void* d_out, int out_size)
{
    const float* x = (const float*)d_in[0];
    const float* y = (const float*)d_in[1];
    float* out = (float*)d_out;

    dim3 block(TPX, 1, 1);                            // 128 threads
    dim3 grid(IMG / (2 * TPX), IMG / ROWS, 16 * 3);   // 2 x 32 x 48 = 3072
    ssim_kernel<<<grid, block>>>(x, y, out);
}